// round 10
// baseline (speedup 1.0000x reference)
#include <cuda_runtime.h>
#include <math.h>
#include <stdint.h>

// Problem constants
#define B_ 8
#define L_ 512
#define K_ 512
#define D_ 64
#define M_ 64
#define N_ 64
#define P_ 64

#define SWS 516         // sW row stride (floats)
#define SKS 68          // sK row stride (floats) -> conflict-free 16B LDS phases

typedef unsigned long long ull;

// ---- packed f32x2 helpers (sm_103a) ----
#define FMA2ACC(acc, a, b) \
    asm("fma.rn.f32x2 %0, %1, %2, %0;" : "+l"(acc) : "l"(a), "l"(b))

static __device__ __forceinline__ ull fdup(float v) {
    ull u; asm("mov.b64 %0, {%1, %1};" : "=l"(u) : "f"(v)); return u;
}
static __device__ __forceinline__ float2 f2unpack(ull u) {
    float2 v; asm("mov.b64 {%0, %1}, %2;" : "=f"(v.x), "=f"(v.y) : "l"(u)); return v;
}
// 128-bit global load as two packed f32x2 (no re-pack needed)
static __device__ __forceinline__ void ldg2(const float* p, ull& a, ull& b) {
    asm("ld.global.nc.v2.u64 {%0,%1}, [%2];" : "=l"(a), "=l"(b) : "l"(p));
}
// 128-bit shared load as two packed f32x2
static __device__ __forceinline__ void lds2(const float* p, ull& a, ull& b) {
    unsigned s = (unsigned)__cvta_generic_to_shared((void*)p);
    asm("ld.shared.v2.u64 {%0,%1}, [%2];" : "=l"(a), "=l"(b) : "r"(s));
}

// Scratch
__device__ float g_vkc[B_ * K_ * N_];   // vkc[b,k,n] (1 MB)
__device__ float g_tmp[B_ * L_ * N_];   // tmp[b,l,n] (1 MB)

// ---------------------------------------------------------------------------
// Kernel 1: vkc[b,k,n] = sum_p vk[b,k,p,n] * vexp[b,k,p]   (streams vk once)
// 512 blocks x 128 threads; block = 8 bk-rows; thread = (row r, n-quad n4).
// All loads LDG.128 coalesced; 4 independent FMA2 accumulator chains.
// ---------------------------------------------------------------------------
__global__ __launch_bounds__(128) void vkc_kernel(const float* __restrict__ vk,
                                                  const float* __restrict__ vexp) {
    __shared__ float se[8 * P_];
    const int t = threadIdx.x;
    const int r = t >> 4;
    const int n4 = t & 15;
    const int bk0 = blockIdx.x * 8;

#pragma unroll
    for (int i = 0; i < 4; ++i)
        se[t + i * 128] = vexp[(size_t)bk0 * P_ + t + i * 128];
    __syncthreads();

    const float* base = vk + ((size_t)(bk0 + r) * P_ + 0) * N_ + n4 * 4;
    const float* ser = se + r * P_;

    ull a0 = 0, a1 = 0, b0 = 0, b1 = 0;
#pragma unroll
    for (int p = 0; p < P_; p += 2) {
        ull x0, x1, y0, y1;
        ldg2(base + p * N_, x0, x1);
        ldg2(base + (p + 1) * N_, y0, y1);
        ull w0 = fdup(ser[p]);
        ull w1 = fdup(ser[p + 1]);
        FMA2ACC(a0, w0, x0); FMA2ACC(a1, w0, x1);
        FMA2ACC(b0, w1, y0); FMA2ACC(b1, w1, y1);
    }
    float2 p0 = f2unpack(a0), p1 = f2unpack(b0);
    float2 p2 = f2unpack(a1), p3 = f2unpack(b1);
    float4 r4 = make_float4(p0.x + p1.x, p0.y + p1.y, p2.x + p3.x, p2.y + p3.y);
    ((float4*)(g_vkc + (size_t)(bk0 + r) * N_))[n4] = r4;
}

// ---------------------------------------------------------------------------
// Kernel 2: scores + softmax + tmp.  One block = 8 l-rows of one b.
// grid = 512, block = 256 (8 warps).  Warp w owns l-row w throughout.
//
// Phase A: q row in registers (32 ull), K staged in padded smem in 64-row
//   chunks; each lane computes 2 full dots per chunk (k = lane, lane+32).
//   No shuffles, no packs.
// Phase B: tmp[l][n] = inv * sum_k e[l][k]*vkc[b][k][n], v2.u64 + f32x2.
// ---------------------------------------------------------------------------
__global__ __launch_bounds__(256) void score_tmp_kernel(const float* __restrict__ q,
                                                        const float* __restrict__ kmat,
                                                        const float* __restrict__ scale_p,
                                                        float* __restrict__ tmp_out) {
    __shared__ float sK[64 * SKS];      // 17408 B
    __shared__ float sW[8 * SWS];       // 16512 B
    __shared__ float sQ[8 * D_];        //  2048 B
    __shared__ float sTmpP[2][8 * N_];  //  4096 B
    __shared__ float sInv[8];

    const int t = threadIdx.x;
    const int warp = t >> 5;
    const int lane = t & 31;
    const int blk = blockIdx.x;         // b*64 + ltile
    const int b = blk >> 6;
    const int bl8 = blk * 8;
    const float scl = *scale_p;

    // ---- stage Q tile ----
    if (t < 128) ((float4*)sQ)[t] = ((const float4*)q)[(size_t)bl8 * 16 + t];
    __syncthreads();

    // ---- q row (l = warp) into registers: 32 packed f32x2 ----
    ull qr[32];
    {
        const float* qp = sQ + warp * D_;
#pragma unroll
        for (int i = 0; i < 16; ++i) lds2(qp + i * 4, qr[2 * i], qr[2 * i + 1]);
    }

    // ---- Phase A: 8 chunks of 64 K-rows ----
    const float4* kg4 = (const float4*)(kmat + (size_t)b * K_ * D_);
    for (int c = 0; c < 8; ++c) {
        // cooperative coalesced load of 64 rows into padded smem
#pragma unroll
        for (int i = 0; i < 4; ++i) {
            const int idx = t + i * 256;        // 0..1023
            const int row = idx >> 4, c4 = idx & 15;
            ((float4*)sK)[row * (SKS / 4) + c4] = kg4[(size_t)(c * 64 + row) * 16 + c4];
        }
        __syncthreads();

#pragma unroll
        for (int j = 0; j < 2; ++j) {
            const int kk = j * 32 + lane;
            const float* kp = sK + kk * SKS;
            ull acc = 0;
#pragma unroll
            for (int i = 0; i < 16; ++i) {
                ull k0, k1;
                lds2(kp + i * 4, k0, k1);
                FMA2ACC(acc, k0, qr[2 * i]);
                FMA2ACC(acc, k1, qr[2 * i + 1]);
            }
            float2 f = f2unpack(acc);
            sW[warp * SWS + c * 64 + kk] = (f.x + f.y) * scl;
        }
        __syncthreads();
    }

    // ---- softmax, warp w owns row w ----
    {
        float* row = sW + warp * SWS;
        float mx = -1e30f;
#pragma unroll
        for (int i = 0; i < K_ / 32; ++i) mx = fmaxf(mx, row[lane + i * 32]);
#pragma unroll
        for (int o = 16; o; o >>= 1) mx = fmaxf(mx, __shfl_xor_sync(0xFFFFFFFFu, mx, o));
        float s = 0.f;
#pragma unroll
        for (int i = 0; i < K_ / 32; ++i) {
            float e = __expf(row[lane + i * 32] - mx);
            row[lane + i * 32] = e;
            s += e;
        }
#pragma unroll
        for (int o = 16; o; o >>= 1) s += __shfl_xor_sync(0xFFFFFFFFu, s, o);
        if (lane == 0) sInv[warp] = 1.f / s;
    }
    __syncthreads();

    // ---- Phase B: tmp partials ----
    {
        const int n4 = t & 15;
        const int l = (t >> 4) & 7;
        const int kh = t >> 7;
        const float* vp = g_vkc + ((size_t)b * K_ + kh * 256) * N_ + n4 * 4;
        const float* wrow = sW + l * SWS + kh * 256;
        ull aX0 = 0, aX1 = 0, aY0 = 0, aY1 = 0;
#pragma unroll 8
        for (int k = 0; k < 256; k += 2) {
            float2 wv = *(const float2*)(wrow + k);
            ull v00, v01, v10, v11;
            ldg2(vp + (size_t)k * N_, v00, v01);
            ldg2(vp + (size_t)(k + 1) * N_, v10, v11);
            ull w0 = fdup(wv.x);
            ull w1 = fdup(wv.y);
            FMA2ACC(aX0, w0, v00); FMA2ACC(aX1, w0, v01);
            FMA2ACC(aY0, w1, v10); FMA2ACC(aY1, w1, v11);
        }
        float2 x0 = f2unpack(aX0), x1 = f2unpack(aX1);
        float2 y0 = f2unpack(aY0), y1 = f2unpack(aY1);
        float4 acc = make_float4(x0.x + y0.x, x0.y + y0.y, x1.x + y1.x, x1.y + y1.y);
        ((float4*)(sTmpP[kh] + l * N_))[n4] = acc;
    }
    __syncthreads();

    // ---- combine halves, apply 1/sum, write tmp ----
    if (t < 128) {
        const int l = t >> 4, n4 = t & 15;
        float4 a = ((float4*)(sTmpP[0] + l * N_))[n4];
        float4 c = ((float4*)(sTmpP[1] + l * N_))[n4];
        const float inv = sInv[l];
        float4 r = make_float4((a.x + c.x) * inv, (a.y + c.y) * inv,
                               (a.z + c.z) * inv, (a.w + c.w) * inv);
        ((float4*)(tmp_out + ((size_t)bl8 + l) * N_))[n4] = r;
    }
}

// ---------------------------------------------------------------------------
// Kernel 3: out = LayerNorm(q + vq . tmp).  Streams vq (67 MB) coalesced.
// grid = 2048 x 256; each 128-thread half handles one (b,l) row.
// ---------------------------------------------------------------------------
__global__ __launch_bounds__(256) void out_kernel(const float* __restrict__ q,
                                                  const float* __restrict__ vq,
                                                  const float* __restrict__ gamma,
                                                  const float* __restrict__ beta,
                                                  float* __restrict__ out) {
    __shared__ float sTmp[2][N_];
    __shared__ float sQ[2][D_];
    __shared__ float sAttn[2][M_];

    const int t = threadIdx.x;
    const int h = t >> 7;
    const int tt = t & 127;
    const int bl = blockIdx.x * 2 + h;

    if (tt < 64) sTmp[h][tt] = g_tmp[(size_t)bl * N_ + tt];
    else         sQ[h][tt - 64] = q[(size_t)bl * D_ + (tt - 64)];
    __syncthreads();

    {
        const int n4 = tt & 15;
        ull tv01, tv23;
        lds2(sTmp[h] + n4 * 4, tv01, tv23);
        const float* vqp = vq + (size_t)bl * (M_ * N_);

        ull v[16];
#pragma unroll
        for (int j = 0; j < 8; ++j)
            ldg2(vqp + (size_t)(tt + 128 * j) * 4, v[2 * j], v[2 * j + 1]);

#pragma unroll
        for (int j = 0; j < 8; ++j) {
            ull a2 = 0;
            FMA2ACC(a2, v[2 * j], tv01);
            FMA2ACC(a2, v[2 * j + 1], tv23);
            float2 f = f2unpack(a2);
            float d = f.x + f.y;
            d += __shfl_xor_sync(0xFFFFFFFFu, d, 1);
            d += __shfl_xor_sync(0xFFFFFFFFu, d, 2);
            d += __shfl_xor_sync(0xFFFFFFFFu, d, 4);
            d += __shfl_xor_sync(0xFFFFFFFFu, d, 8);
            if (n4 == 0) sAttn[h][(tt >> 4) + 8 * j] = d;
        }
    }
    __syncthreads();

    if (tt < 32) {
        const int lane = tt;
        const float x0 = sQ[h][lane] + sAttn[h][lane];
        const float x1 = sQ[h][lane + 32] + sAttn[h][lane + 32];
        float s = x0 + x1, ss = x0 * x0 + x1 * x1;
#pragma unroll
        for (int o = 16; o; o >>= 1) {
            s += __shfl_xor_sync(0xFFFFFFFFu, s, o);
            ss += __shfl_xor_sync(0xFFFFFFFFu, ss, o);
        }
        const float mu = s * (1.f / 64.f);
        const float var = ss * (1.f / 64.f) - mu * mu;
        const float r = rsqrtf(var + 1e-3f);
        out[(size_t)bl * M_ + lane] = (x0 - mu) * r * gamma[lane] + beta[lane];
        out[(size_t)bl * M_ + lane + 32] =
            (x1 - mu) * r * gamma[lane + 32] + beta[lane + 32];
    }
}

// ---------------------------------------------------------------------------
extern "C" void kernel_launch(void* const* d_in, const int* in_sizes, int n_in,
                              void* d_out, int out_size) {
    const float* q     = (const float*)d_in[0];
    const float* k     = (const float*)d_in[1];
    const float* vq    = (const float*)d_in[2];
    const float* vk    = (const float*)d_in[3];
    const float* vexp  = (const float*)d_in[4];
    const float* scale = (const float*)d_in[5];
    const float* gamma = (const float*)d_in[6];
    const float* beta  = (const float*)d_in[7];
    float* out = (float*)d_out;

    float* tmp_ptr;
    cudaGetSymbolAddress((void**)&tmp_ptr, g_tmp);

    vkc_kernel<<<B_ * K_ / 8, 128>>>(vk, vexp);
    score_tmp_kernel<<<B_ * L_ / 8, 256>>>(q, k, scale, tmp_ptr);
    out_kernel<<<B_ * L_ / 2, 256>>>(q, vq, gamma, beta, out);
}

// round 12
// speedup vs baseline: 1.2131x; 1.2131x over previous
#include <cuda_runtime.h>
#include <math.h>
#include <stdint.h>

// Problem constants
#define B_ 8
#define L_ 512
#define K_ 512
#define D_ 64
#define M_ 64
#define N_ 64
#define P_ 64

#define SKS 68          // sK row stride (floats): conflict-free 16B LDS phases
#define SWS 516         // score buffer row stride (floats)
#define BWS 520         // kernel-B weight tile row stride (floats, 16B-aligned rows)

typedef unsigned long long ull;

// ---- packed f32x2 helpers (sm_103a) ----
#define FMA2ACC(acc, a, b) \
    asm("fma.rn.f32x2 %0, %1, %2, %0;" : "+l"(acc) : "l"(a), "l"(b))

static __device__ __forceinline__ ull fdup(float v) {
    ull u; asm("mov.b64 %0, {%1, %1};" : "=l"(u) : "f"(v)); return u;
}
static __device__ __forceinline__ float2 f2unpack(ull u) {
    float2 v; asm("mov.b64 {%0, %1}, %2;" : "=f"(v.x), "=f"(v.y) : "l"(u)); return v;
}
static __device__ __forceinline__ void ldg2(const float* p, ull& a, ull& b) {
    asm("ld.global.nc.v2.u64 {%0,%1}, [%2];" : "=l"(a), "=l"(b) : "l"(p));
}
static __device__ __forceinline__ void lds2(const float* p, ull& a, ull& b) {
    unsigned s = (unsigned)__cvta_generic_to_shared((void*)p);
    asm("ld.shared.v2.u64 {%0,%1}, [%2];" : "=l"(a), "=l"(b) : "r"(s));
}

// Scratch (device globals: allocation-free)
__device__ float g_vkc[B_ * K_ * N_];   // vkc[b,k,n]            (1 MB)
__device__ float g_w[B_ * L_ * K_];     // exp weights (unnorm)  (8 MB)
__device__ float g_winv[B_ * L_];       // per-row 1/sum         (16 KB)

// ---------------------------------------------------------------------------
// Kernel A (fat): 1536 blocks x 256 threads.
//   blocks with bid%3 != 2  -> vkc work   (1024 blocks, 4 bk-rows each)
//   blocks with bid%3 == 2  -> scores+softmax (512 blocks, 8 l-rows each)
// The two block types are independent; interleaving overlaps vkc's HBM
// stream with the score blocks' smem/FMA work.
// ---------------------------------------------------------------------------
union SmemA {
    struct {
        float sK[64 * SKS];     // 17408 B : K chunk (64 rows, padded)
        float sWa[8 * SWS];     // 16512 B : scores (both d-halves combined)
        float sQ[8 * D_];       //  2048 B
        float sInv[8];
    } sc;
    struct {
        float4 part[256];       //  4096 B : P-split partials
        float se[256];          //  1024 B : vexp rows
    } vk;
};

__global__ __launch_bounds__(256, 2) void fatA(const float* __restrict__ vk,
                                               const float* __restrict__ vexp,
                                               const float* __restrict__ q,
                                               const float* __restrict__ kmat,
                                               const float* __restrict__ scale_p) {
    __shared__ SmemA sm;
    const int bid = blockIdx.x;
    const int t = threadIdx.x;
    const int r3 = bid % 3;

    if (r3 != 2) {
        // ================= vkc block: 4 bk-rows, P-split 4 =================
        const int vi = (bid / 3) * 2 + r3;      // 0..1023
        const int bk0 = vi * 4;
        const int row = t >> 6;                 // 0..3
        const int u = t & 63;
        const int ps = u >> 4;                  // P quarter 0..3
        const int n4 = u & 15;                  // float4 of n

        sm.vk.se[t] = vexp[(size_t)bk0 * P_ + t];
        __syncthreads();

        const float* base = vk + ((size_t)(bk0 + row) * P_ + ps * 16) * N_ + n4 * 4;
        const float* ser = sm.vk.se + row * P_ + ps * 16;

        ull a0 = 0, a1 = 0, b0 = 0, b1 = 0;
#pragma unroll
        for (int i = 0; i < 16; i += 2) {
            ull x0, x1, y0, y1;
            ldg2(base + i * N_, x0, x1);
            ldg2(base + (i + 1) * N_, y0, y1);
            ull w0 = fdup(ser[i]);
            ull w1 = fdup(ser[i + 1]);
            FMA2ACC(a0, w0, x0); FMA2ACC(a1, w0, x1);
            FMA2ACC(b0, w1, y0); FMA2ACC(b1, w1, y1);
        }
        float2 p0 = f2unpack(a0), p1 = f2unpack(b0);
        float2 p2 = f2unpack(a1), p3 = f2unpack(b1);
        sm.vk.part[t] = make_float4(p0.x + p1.x, p0.y + p1.y, p2.x + p3.x, p2.y + p3.y);
        __syncthreads();

        if (t < 64) {
            const int r = t >> 4, n = t & 15;
            float4 s0 = sm.vk.part[r * 64 + n];
            float4 s1 = sm.vk.part[r * 64 + 16 + n];
            float4 s2 = sm.vk.part[r * 64 + 32 + n];
            float4 s3 = sm.vk.part[r * 64 + 48 + n];
            float4 o = make_float4(s0.x + s1.x + s2.x + s3.x,
                                   s0.y + s1.y + s2.y + s3.y,
                                   s0.z + s1.z + s2.z + s3.z,
                                   s0.w + s1.w + s2.w + s3.w);
            ((float4*)(g_vkc + (size_t)(bk0 + r) * N_))[n] = o;
        }
    } else {
        // ================= score block: 8 l-rows of one b =================
        const int si = bid / 3;                 // 0..511
        const int b = si >> 6;
        const int bl8 = si * 8;
        const int warp = t >> 5;
        const int lane = t & 31;
        const int lp = warp & 3;                // l-pair: rows 2lp, 2lp+1
        const int dh = warp >> 2;               // d-half 0/1
        const float scl = *scale_p;

        if (t < 128)
            ((float4*)sm.sc.sQ)[t] = ((const float4*)q)[(size_t)bl8 * 16 + t];
        __syncthreads();

        // q registers: 2 rows x 32 d (this warp's d-half) = 32 ull
        ull q0[16], q1[16];
        {
            const float* qp0 = sm.sc.sQ + (2 * lp) * D_ + dh * 32;
            const float* qp1 = sm.sc.sQ + (2 * lp + 1) * D_ + dh * 32;
#pragma unroll
            for (int i = 0; i < 8; ++i) {
                lds2(qp0 + i * 4, q0[2 * i], q0[2 * i + 1]);
                lds2(qp1 + i * 4, q1[2 * i], q1[2 * i + 1]);
            }
        }

        const float4* kg4 = (const float4*)(kmat + (size_t)b * K_ * D_);
        for (int c = 0; c < 8; ++c) {
            // stage 64 K-rows (coalesced)
#pragma unroll
            for (int i = 0; i < 4; ++i) {
                const int idx = t + i * 256;
                const int row = idx >> 4, c4 = idx & 15;
                ((float4*)sm.sc.sK)[row * (SKS / 4) + c4] =
                    kg4[(size_t)(c * 64 + row) * 16 + c4];
            }
            __syncthreads();

            // each lane: 2 k-columns, partial dots over this warp's d-half
            float pr[2][2];
#pragma unroll
            for (int j = 0; j < 2; ++j) {
                const int kk = j * 32 + lane;
                const float* kp = sm.sc.sK + kk * SKS + dh * 32;
                ull acc0 = 0, acc1 = 0;
#pragma unroll
                for (int i = 0; i < 8; ++i) {
                    ull k0, k1;
                    lds2(kp + i * 4, k0, k1);
                    FMA2ACC(acc0, k0, q0[2 * i]); FMA2ACC(acc0, k1, q0[2 * i + 1]);
                    FMA2ACC(acc1, k0, q1[2 * i]); FMA2ACC(acc1, k1, q1[2 * i + 1]);
                }
                float2 f0 = f2unpack(acc0), f1 = f2unpack(acc1);
                pr[j][0] = f0.x + f0.y;
                pr[j][1] = f1.x + f1.y;
            }
            // combine d-halves: dh0 writes, then dh1 accumulates
            if (dh == 0) {
#pragma unroll
                for (int j = 0; j < 2; ++j) {
                    const int kk = j * 32 + lane;
                    sm.sc.sWa[(2 * lp) * SWS + c * 64 + kk] = pr[j][0];
                    sm.sc.sWa[(2 * lp + 1) * SWS + c * 64 + kk] = pr[j][1];
                }
            }
            __syncthreads();
            if (dh == 1) {
#pragma unroll
                for (int j = 0; j < 2; ++j) {
                    const int kk = j * 32 + lane;
                    sm.sc.sWa[(2 * lp) * SWS + c * 64 + kk] += pr[j][0];
                    sm.sc.sWa[(2 * lp + 1) * SWS + c * 64 + kk] += pr[j][1];
                }
            }
            __syncthreads();
        }

        // ---- softmax: warp w owns row w ----
        {
            float* ra = sm.sc.sWa + warp * SWS;
            float v[16];
            float mx = -1e30f;
#pragma unroll
            for (int i = 0; i < 16; ++i) {
                v[i] = ra[lane + i * 32] * scl;
                mx = fmaxf(mx, v[i]);
            }
#pragma unroll
            for (int o = 16; o; o >>= 1) mx = fmaxf(mx, __shfl_xor_sync(0xFFFFFFFFu, mx, o));
            float s = 0.f;
#pragma unroll
            for (int i = 0; i < 16; ++i) {
                float e = __expf(v[i] - mx);
                ra[lane + i * 32] = e;
                s += e;
            }
#pragma unroll
            for (int o = 16; o; o >>= 1) s += __shfl_xor_sync(0xFFFFFFFFu, s, o);
            if (lane == 0) sm.sc.sInv[warp] = 1.f / s;
        }
        __syncthreads();

        // ---- write weights + inv to global (coalesced float4) ----
#pragma unroll
        for (int i = 0; i < 4; ++i) {
            const int idx = t + i * 256;          // 0..1023 float4 slots
            const int row = idx >> 7, c4 = idx & 127;
            float4 wv = *(const float4*)(sm.sc.sWa + row * SWS + c4 * 4);
            ((float4*)g_w)[(size_t)(bl8 + row) * 128 + c4] = wv;
        }
        if (t < 8) g_winv[bl8 + t] = sm.sc.sInv[t];
    }
}

// ---------------------------------------------------------------------------
// Kernel B (fused): tmp (weights . vkc) + vq stream + residual + LayerNorm.
// 512 blocks x 256 threads; block = 8 l-rows of one b.
// ---------------------------------------------------------------------------
__global__ __launch_bounds__(256) void fusedB(const float* __restrict__ q,
                                              const float* __restrict__ vq,
                                              const float* __restrict__ gamma,
                                              const float* __restrict__ beta,
                                              float* __restrict__ out) {
    __shared__ float sW[8 * BWS];       // 16640 B : exp weights tile
    __shared__ float sQ[8 * D_];        //  2048 B
    __shared__ float sTmpP[2][8 * N_];  //  4096 B
    __shared__ float sTmpF[8 * N_];     //  2048 B
    __shared__ float sAttn[8 * M_];     //  2048 B
    __shared__ float sInv[8];

    const int t = threadIdx.x;
    const int blk = blockIdx.x;
    const int b = blk >> 6;
    const int bl8 = blk * 8;

    // ---- stage q rows, weight tile, inv ----
    if (t < 128) ((float4*)sQ)[t] = ((const float4*)q)[(size_t)bl8 * 16 + t];
    if (t < 8) sInv[t] = g_winv[bl8 + t];
#pragma unroll
    for (int i = 0; i < 4; ++i) {
        const int idx = t + i * 256;
        const int row = idx >> 7, c4 = idx & 127;
        float4 wv = ((const float4*)g_w)[(size_t)(bl8 + row) * 128 + c4];
        *(float4*)(sW + row * BWS + c4 * 4) = wv;
    }
    __syncthreads();

    // ---- Phase B: tmp partials over k-halves ----
    {
        const int n4 = t & 15;
        const int l = (t >> 4) & 7;
        const int kh = t >> 7;
        const float* vp = g_vkc + ((size_t)b * K_ + kh * 256) * N_ + n4 * 4;
        const float* wrow = sW + l * BWS + kh * 256;
        ull aX0 = 0, aX1 = 0, aY0 = 0, aY1 = 0;
#pragma unroll 8
        for (int k = 0; k < 256; k += 2) {
            float2 wv = *(const float2*)(wrow + k);
            ull v00, v01, v10, v11;
            ldg2(vp + (size_t)k * N_, v00, v01);
            ldg2(vp + (size_t)(k + 1) * N_, v10, v11);
            ull w0 = fdup(wv.x);
            ull w1 = fdup(wv.y);
            FMA2ACC(aX0, w0, v00); FMA2ACC(aX1, w0, v01);
            FMA2ACC(aY0, w1, v10); FMA2ACC(aY1, w1, v11);
        }
        float2 x0 = f2unpack(aX0), x1 = f2unpack(aX1);
        float2 y0 = f2unpack(aY0), y1 = f2unpack(aY1);
        float4 acc = make_float4(x0.x + y0.x, x0.y + y0.y, x1.x + y1.x, x1.y + y1.y);
        ((float4*)(sTmpP[kh] + l * N_))[n4] = acc;
    }
    __syncthreads();
    if (t < 128) {
        const int l = t >> 4, n4 = t & 15;
        float4 a = ((float4*)(sTmpP[0] + l * N_))[n4];
        float4 c = ((float4*)(sTmpP[1] + l * N_))[n4];
        const float inv = sInv[l];
        float4 r = make_float4((a.x + c.x) * inv, (a.y + c.y) * inv,
                               (a.z + c.z) * inv, (a.w + c.w) * inv);
        ((float4*)(sTmpF + l * N_))[n4] = r;
    }
    __syncthreads();

    // ---- Phase C: attn = vq . tmp, 2 rows per iteration (halves) ----
    {
        const int h = t >> 7;
        const int tt = t & 127;
        const int n4 = tt & 15;
#pragma unroll
        for (int it = 0; it < 4; ++it) {
            const int l = it * 2 + h;
            ull tv01, tv23;
            lds2(sTmpF + l * N_ + n4 * 4, tv01, tv23);
            const float* vqp = vq + (size_t)(bl8 + l) * (M_ * N_);
            ull v[16];
#pragma unroll
            for (int j = 0; j < 8; ++j)
                ldg2(vqp + (size_t)(tt + 128 * j) * 4, v[2 * j], v[2 * j + 1]);
#pragma unroll
            for (int j = 0; j < 8; ++j) {
                ull a2 = 0;
                FMA2ACC(a2, v[2 * j], tv01);
                FMA2ACC(a2, v[2 * j + 1], tv23);
                float2 f = f2unpack(a2);
                float d = f.x + f.y;
                d += __shfl_xor_sync(0xFFFFFFFFu, d, 1);
                d += __shfl_xor_sync(0xFFFFFFFFu, d, 2);
                d += __shfl_xor_sync(0xFFFFFFFFu, d, 4);
                d += __shfl_xor_sync(0xFFFFFFFFu, d, 8);
                if (n4 == 0) sAttn[l * M_ + (tt >> 4) + 8 * j] = d;
            }
        }
    }
    __syncthreads();

    // ---- residual + LayerNorm: warp w owns row w ----
    {
        const int warp = t >> 5, lane = t & 31;
        const float x0 = sQ[warp * D_ + lane] + sAttn[warp * M_ + lane];
        const float x1 = sQ[warp * D_ + lane + 32] + sAttn[warp * M_ + lane + 32];
        float s = x0 + x1, ss = x0 * x0 + x1 * x1;
#pragma unroll
        for (int o = 16; o; o >>= 1) {
            s += __shfl_xor_sync(0xFFFFFFFFu, s, o);
            ss += __shfl_xor_sync(0xFFFFFFFFu, ss, o);
        }
        const float mu = s * (1.f / 64.f);
        const float var = ss * (1.f / 64.f) - mu * mu;
        const float r = rsqrtf(var + 1e-3f);
        out[(size_t)(bl8 + warp) * M_ + lane] = (x0 - mu) * r * gamma[lane] + beta[lane];
        out[(size_t)(bl8 + warp) * M_ + lane + 32] =
            (x1 - mu) * r * gamma[lane + 32] + beta[lane + 32];
    }
}

// ---------------------------------------------------------------------------
extern "C" void kernel_launch(void* const* d_in, const int* in_sizes, int n_in,
                              void* d_out, int out_size) {
    const float* q     = (const float*)d_in[0];
    const float* k     = (const float*)d_in[1];
    const float* vq    = (const float*)d_in[2];
    const float* vk    = (const float*)d_in[3];
    const float* vexp  = (const float*)d_in[4];
    const float* scale = (const float*)d_in[5];
    const float* gamma = (const float*)d_in[6];
    const float* beta  = (const float*)d_in[7];
    float* out = (float*)d_out;

    fatA<<<1536, 256>>>(vk, vexp, q, k, scale);
    fusedB<<<512, 256>>>(q, vq, gamma, beta, out);
}